// round 9
// baseline (speedup 1.0000x reference)
#include <cuda_runtime.h>

// Problem constants
#define BB   256   // batch
#define NN   196   // tokens
#define QR   49    // rows per copy work-unit (quarter batch)
#define NU   1024  // copy units = BB*4
#define DD   768   // dim
#define PP   32    // pool size
#define TOPK 5
#define MM   128   // PP*4 rows of patch-embed GEMM
#define KDIM 768   // 3*16*16

#define NBLK 296                       // grid = 2 blocks/SM exactly
#define TICKS_PER_LAUNCH (NU + NBLK)   // every launch consumes exactly this many

// Output layout (flattened tuple, float32):
//   prompted_embedding (256,216,768) | reduce_sim (1) | similarity (256,32) | idx (256,5)
#define O_RS  (42467328ll)
#define O_SIM (O_RS + 1)          // odd float offset -> 4B-aligned only; scalar stores
#define O_IDX (O_SIM + (long long)BB * PP)

// Scratch (static device globals — no allocation allowed).
// ALL arrays touched through float4 are force-aligned to 16B.
__device__ __align__(16) float g_pembed[MM * DD];    // patch-embed result (128,768)
__device__ __align__(16) float g_pnorm[PP * DD];     // l2-normalized prompt_key
__device__ __align__(16) float g_mpart[4][BB][DD];   // per-quarter partial row sums
__device__ __align__(16) float g_rs[BB];             // per-batch top-5 sim sums
__device__ int      g_bcnt[BB];           // per-batch quarter-arrival counters
__device__ int      g_ready;              // producer completion counter (reset by last tail)
__device__ int      g_counter;            // tail completion counter (reset by last tail)
__device__ unsigned g_ticket;             // monotonic work ticket (modulo per launch)

// ---------------------------------------------------------------------------
// Persistent fused kernel: 296 blocks x 256 threads (exactly 2/SM, one wave).
//   blocks [0,48): patch-embed GEMM -> g_pembed, signal g_ready, then join pool
//   block  48:     prompt_key L2 norm -> g_pnorm, signal g_ready, then join pool
//   all blocks:    steal 49-row copy units via g_ticket; the 4th finisher of a
//                  batch combines partials (fixed order -> deterministic) and
//                  runs sim+top5+gather for that batch.
// ---------------------------------------------------------------------------
__global__ void __launch_bounds__(256) fused_kernel(
    const float* __restrict__ x,       // (256,196,768)
    const float* __restrict__ prompt,  // (32,3,32,32)
    const float* __restrict__ pkey,    // (32,768)
    const float* __restrict__ w,       // (768,3,16,16) == (768,768) row-major
    const float* __restrict__ bias,    // (768)
    float* __restrict__ out)
{
    const int bx = blockIdx.x;
    const int t  = threadIdx.x;
    const int warp = t >> 5, lane = t & 31;
    const unsigned FULL = 0xffffffffu;

    if (bx < 48) {
        // ---- patch-embed GEMM: g_pembed[m,d] = sum_k A[m,k]*W[d,k] + bias[d]
        __shared__ __align__(16) float As[32][33];
        __shared__ __align__(16) float Ws[64][33];
        const int m0 = (bx / 12) * 32;
        const int n0 = (bx % 12) * 64;
        const int tx = t & 15;    // 4 output cols each
        const int ty = t >> 4;    // 2 output rows each
        float acc[2][4] = {{0.f,0.f,0.f,0.f},{0.f,0.f,0.f,0.f}};

        const float4* w4 = reinterpret_cast<const float4*>(w);

        for (int k0 = 0; k0 < KDIM; k0 += 32) {
            #pragma unroll
            for (int s = 0; s < 4; s++) {
                int e  = s * 256 + t;
                int mm = e >> 5;
                int kk = e & 31;
                int m  = m0 + mm;
                int p  = m >> 2;
                int l  = m & 3;
                int py = l >> 1, px = l & 1;
                int k  = k0 + kk;
                int c  = k >> 8;
                int rem = k & 255;
                int ii = rem >> 4, jj = rem & 15;
                As[mm][kk] = prompt[((size_t)(p * 3 + c) * 32 + py * 16 + ii) * 32
                                    + px * 16 + jj];
            }
            #pragma unroll
            for (int s = 0; s < 2; s++) {
                int v  = s * 256 + t;        // 0..511
                int dd = v >> 3;             // 0..63
                int kv = v & 7;
                float4 f = w4[(size_t)(n0 + dd) * 192 + (k0 >> 2) + kv];
                Ws[dd][kv * 4 + 0] = f.x;
                Ws[dd][kv * 4 + 1] = f.y;
                Ws[dd][kv * 4 + 2] = f.z;
                Ws[dd][kv * 4 + 3] = f.w;
            }
            __syncthreads();
            #pragma unroll
            for (int kk = 0; kk < 32; kk++) {
                float a0 = As[ty * 2 + 0][kk];
                float a1 = As[ty * 2 + 1][kk];
                #pragma unroll
                for (int j = 0; j < 4; j++) {
                    float wv = Ws[tx * 4 + j][kk];
                    acc[0][j] += a0 * wv;
                    acc[1][j] += a1 * wv;
                }
            }
            __syncthreads();
        }
        #pragma unroll
        for (int r = 0; r < 2; r++) {
            #pragma unroll
            for (int j = 0; j < 4; j++) {
                int m = m0 + ty * 2 + r;
                int d = n0 + tx * 4 + j;
                g_pembed[m * DD + d] = acc[r][j] + bias[d];
            }
        }
        __syncthreads();
        __threadfence();
        if (t == 0) atomicAdd(&g_ready, 1);

    } else if (bx == 48) {
        // ---- prompt_key L2 normalize: 8 warps x 4 rows
        for (int p = warp; p < PP; p += 8) {
            const float* row = pkey + (size_t)p * DD;
            float sq = 0.f;
            for (int k = lane; k < DD; k += 32) { float v = row[k]; sq += v * v; }
            #pragma unroll
            for (int o = 16; o; o >>= 1) sq += __shfl_xor_sync(FULL, sq, o);
            float rs = rsqrtf(fmaxf(sq, 1e-12f));
            for (int k = lane; k < DD; k += 32) g_pnorm[p * DD + k] = row[k] * rs;
        }
        __syncthreads();
        __threadfence();
        if (t == 0) atomicAdd(&g_ready, 1);
    }

    // ===================== persistent work-stealing copy pool =================
    __shared__ __align__(16) float sx[DD];
    __shared__ float s_red[8];
    __shared__ float s_sim[PP];
    __shared__ int   s_idx[TOPK];
    __shared__ unsigned s_u;
    __shared__ int   s_go, s_last;

    for (;;) {
        if (t == 0) s_u = atomicAdd(&g_ticket, 1u) % TICKS_PER_LAUNCH;
        __syncthreads();
        const unsigned u = s_u;
        if (u >= NU) break;                    // exactly one overflow grab/block

        const int b  = (int)(u >> 2);
        const int q  = (int)(u & 3);
        const int r0 = q * QR;                 // starting row within batch

        // ---- copy 49 rows -> out rows [20+r0, 20+r0+49) + partial sums
        if (t < 192) {
            const float4* src = reinterpret_cast<const float4*>(x)
                                + ((size_t)b * NN + r0) * 192 + t;
            float4* dst = reinterpret_cast<float4*>(out)
                          + ((size_t)b * 216 + 20 + r0) * 192 + t;
            float4 acc = make_float4(0.f, 0.f, 0.f, 0.f);
            #pragma unroll 1
            for (int n = 0; n < QR; n += 7) {     // 49 = 7 * 7, deep MLP
                float4 v[7];
                #pragma unroll
                for (int e = 0; e < 7; e++) v[e] = __ldcs(&src[(size_t)(n + e) * 192]);
                #pragma unroll
                for (int e = 0; e < 7; e++) {
                    __stcs(&dst[(size_t)(n + e) * 192], v[e]);
                    acc.x += v[e].x; acc.y += v[e].y;
                    acc.z += v[e].z; acc.w += v[e].w;
                }
            }
            reinterpret_cast<float4*>(g_mpart[q][b])[t] = acc;
        }
        __syncthreads();
        __threadfence();
        if (t == 0) {
            int old = atomicAdd(&g_bcnt[b], 1);
            s_go = (old == 3);                 // 4th arriver runs the tail
        }
        __syncthreads();
        if (!s_go) continue;

        // =================== per-batch tail (deterministic) ==================
        __threadfence();                       // acquire sibling partials
        if (t == 0) g_bcnt[b] = 0;             // reset for next launch
        if (t < 192) {
            const float4* p0 = reinterpret_cast<const float4*>(g_mpart[0][b]);
            const float4* p1 = reinterpret_cast<const float4*>(g_mpart[1][b]);
            const float4* p2 = reinterpret_cast<const float4*>(g_mpart[2][b]);
            const float4* p3 = reinterpret_cast<const float4*>(g_mpart[3][b]);
            float4 a = p0[t], c1 = p1[t], c2 = p2[t], c3 = p3[t];
            const float inv = 1.0f / 196.0f;   // fixed order -> deterministic
            a.x = ((a.x + c1.x) + (c2.x + c3.x)) * inv;
            a.y = ((a.y + c1.y) + (c2.y + c3.y)) * inv;
            a.z = ((a.z + c1.z) + (c2.z + c3.z)) * inv;
            a.w = ((a.w + c1.w) + (c2.w + c3.w)) * inv;
            reinterpret_cast<float4*>(sx)[t] = a;
        }

        // ---- wait for GEMM + pnorm producers (never wait on anyone; safe)
        if (t == 0) {
            while (atomicAdd(&g_ready, 0) < 49) { }
        }
        __syncthreads();
        __threadfence();

        // ---- squared norm of mean (from SMEM)
        float sq = 0.f;
        #pragma unroll
        for (int i = 0; i < 3; i++) {
            float v = sx[t + i * 256];
            sq += v * v;
        }
        #pragma unroll
        for (int o = 16; o; o >>= 1) sq += __shfl_xor_sync(FULL, sq, o);
        if (lane == 0) s_red[warp] = sq;
        __syncthreads();
        float rv = (lane < 8) ? s_red[lane] : 0.f;
        #pragma unroll
        for (int o = 4; o; o >>= 1) rv += __shfl_xor_sync(FULL, rv, o);
        const float rs = rsqrtf(fmaxf(__shfl_sync(FULL, rv, 0), 1e-12f));

        // ---- similarity: warp w owns pool rows 4w..4w+3, interleaved dots
        {
            const float* __restrict__ pn0 = g_pnorm + (size_t)(warp * 4 + 0) * DD;
            const float* __restrict__ pn1 = g_pnorm + (size_t)(warp * 4 + 1) * DD;
            const float* __restrict__ pn2 = g_pnorm + (size_t)(warp * 4 + 2) * DD;
            const float* __restrict__ pn3 = g_pnorm + (size_t)(warp * 4 + 3) * DD;
            float d0 = 0.f, d1 = 0.f, d2 = 0.f, d3 = 0.f;
            #pragma unroll
            for (int i = 0; i < DD / 32; i++) {      // fully unrolled -> MLP high
                int k = lane + i * 32;
                float xv = sx[k];
                d0 += xv * __ldg(pn0 + k);
                d1 += xv * __ldg(pn1 + k);
                d2 += xv * __ldg(pn2 + k);
                d3 += xv * __ldg(pn3 + k);
            }
            #pragma unroll
            for (int o = 16; o; o >>= 1) {
                d0 += __shfl_xor_sync(FULL, d0, o);
                d1 += __shfl_xor_sync(FULL, d1, o);
                d2 += __shfl_xor_sync(FULL, d2, o);
                d3 += __shfl_xor_sync(FULL, d3, o);
            }
            if (lane == 0) {
                int p = warp * 4;
                float v0 = d0 * rs, v1 = d1 * rs, v2 = d2 * rs, v3 = d3 * rs;
                s_sim[p + 0] = v0; s_sim[p + 1] = v1;
                s_sim[p + 2] = v2; s_sim[p + 3] = v3;
                float* so = out + O_SIM + (size_t)b * PP + p;   // 4B-aligned only
                so[0] = v0; so[1] = v1; so[2] = v2; so[3] = v3;
            }
        }
        __syncthreads();

        // ---- top-5 (warp 0): iterative argmax, lower index wins ties
        if (warp == 0) {
            float v = s_sim[lane];
            unsigned sel = 0u;
            float lsum = 0.f;
            #pragma unroll
            for (int k = 0; k < TOPK; k++) {
                float bv = ((sel >> lane) & 1u) ? -__int_as_float(0x7f800000) : v;
                int   bi = lane;
                #pragma unroll
                for (int o = 16; o; o >>= 1) {
                    float ov = __shfl_xor_sync(FULL, bv, o);
                    int   oi = __shfl_xor_sync(FULL, bi, o);
                    if (ov > bv || (ov == bv && oi < bi)) { bv = ov; bi = oi; }
                }
                sel |= 1u << bi;
                if (lane == 0) {
                    s_idx[k] = bi;
                    out[O_IDX + (size_t)b * TOPK + k] = (float)bi;
                    lsum += bv;
                }
            }
            if (lane == 0) g_rs[b] = lsum;
        }
        __syncthreads();

        // ---- gather 20 rows (5 prompts x 4 patches) into out rows [0,20)
        const float4* pe4 = reinterpret_cast<const float4*>(g_pembed);
        float4* ob4 = reinterpret_cast<float4*>(out) + (size_t)b * 216 * 192;
        #pragma unroll
        for (int e = t; e < 20 * 192; e += 256) {
            int j = e / 192;          // output row 0..19
            int c = e - j * 192;      // float4 column
            int i = s_idx[j >> 2];    // selected prompt
            int row = i * 4 + (j & 3);
            ob4[(size_t)j * 192 + c] = __ldg(pe4 + (size_t)row * 192 + c);
        }

        // ---- deterministic reduce_sim: last tail sums g_rs in fixed order
        if (t == 0) {
            __threadfence();
            int old = atomicAdd(&g_counter, 1);
            s_last = (old == BB - 1);
        }
        __syncthreads();
        if (s_last) {
            __threadfence();
            float v = g_rs[t];
            #pragma unroll
            for (int o = 16; o; o >>= 1) v += __shfl_xor_sync(FULL, v, o);
            if (lane == 0) s_red[warp] = v;
            __syncthreads();
            if (t == 0) {
                float tot = 0.f;
                #pragma unroll
                for (int wv = 0; wv < 8; wv++) tot += s_red[wv];
                out[O_RS] = tot / (float)BB;
                g_counter = 0;                 // reset for next launch
                g_ready   = 0;                 // (g_ticket handled by modulo)
            }
        }
    }
}

// ---------------------------------------------------------------------------
extern "C" void kernel_launch(void* const* d_in, const int* in_sizes, int n_in,
                              void* d_out, int out_size)
{
    const float* x      = (const float*)d_in[0];  // x_embed  (256,196,768)
    const float* prompt = (const float*)d_in[1];  // prompt   (32,3,32,32)
    const float* pkey   = (const float*)d_in[2];  // prompt_key (32,768)
    const float* w      = (const float*)d_in[3];  // conv_w   (768,3,16,16)
    const float* bias   = (const float*)d_in[4];  // conv_b   (768)
    float* out = (float*)d_out;

    fused_kernel<<<NBLK, 256>>>(x, prompt, pkey, w, bias, out);
}

// round 10
// speedup vs baseline: 1.0263x; 1.0263x over previous
#include <cuda_runtime.h>

// Problem constants
#define BB   256   // batch
#define NN   196   // tokens
#define DD   768   // dim
#define PP   32    // pool size
#define TOPK 5
#define MM   128   // PP*4 rows of patch-embed GEMM
#define KDIM 768   // 3*16*16

// Output layout (flattened tuple, float32):
//   prompted_embedding (256,216,768) | reduce_sim (1) | similarity (256,32) | idx (256,5)
#define O_RS  (42467328ll)
#define O_SIM (O_RS + 1)          // odd float offset -> 4B-aligned only; scalar stores
#define O_IDX (O_SIM + (long long)BB * PP)

// Scratch (static device globals — no allocation allowed); float4-touched => align 16
__device__ __align__(16) float g_pembed[MM * DD];   // patch-embed result (128,768)
__device__ __align__(16) float g_mean[BB * DD];     // per-batch mean of x_embed
__device__ __align__(16) float g_pnorm[PP * DD];    // l2-normalized prompt_key
__device__ __align__(16) float g_rs[BB];            // per-batch top-5 sim sums
__device__ int   g_idx[BB * TOPK];
__device__ int   g_counter;                         // sim-kernel completion counter

// ---------------------------------------------------------------------------
// Mega kernel (exact R2 structure — measured ~6.1 TB/s):
//   blocks [0,48):  patch-embed GEMM  (M=128,N=768,K=768), 32x64 tiles
//   block  48:      prompt_key L2 normalize
//   blocks [49,305): per-batch copy x_embed -> out rows [20,216) + mean accum
// ---------------------------------------------------------------------------
__global__ __launch_bounds__(256) void mega_kernel(
    const float* __restrict__ x,       // (256,196,768)
    const float* __restrict__ prompt,  // (32,3,32,32)
    const float* __restrict__ pkey,    // (32,768)
    const float* __restrict__ w,       // (768,3,16,16) == (768,768) row-major
    const float* __restrict__ bias,    // (768)
    float* __restrict__ out)
{
    const int bx = blockIdx.x;
    const int t  = threadIdx.x;

    if (bx < 48) {
        __shared__ __align__(16) float As[32][33];
        __shared__ __align__(16) float Ws[64][33];
        const int m0 = (bx / 12) * 32;
        const int n0 = (bx % 12) * 64;
        const int tx = t & 15;
        const int ty = t >> 4;
        float acc[2][4] = {{0.f,0.f,0.f,0.f},{0.f,0.f,0.f,0.f}};

        const float4* w4 = reinterpret_cast<const float4*>(w);

        for (int k0 = 0; k0 < KDIM; k0 += 32) {
            #pragma unroll
            for (int s = 0; s < 4; s++) {
                int e  = s * 256 + t;
                int mm = e >> 5;
                int kk = e & 31;
                int m  = m0 + mm;
                int p  = m >> 2;
                int l  = m & 3;
                int py = l >> 1, px = l & 1;
                int k  = k0 + kk;
                int c  = k >> 8;
                int rem = k & 255;
                int ii = rem >> 4, jj = rem & 15;
                As[mm][kk] = prompt[((size_t)(p * 3 + c) * 32 + py * 16 + ii) * 32
                                    + px * 16 + jj];
            }
            #pragma unroll
            for (int s = 0; s < 2; s++) {
                int v  = s * 256 + t;
                int dd = v >> 3;
                int kv = v & 7;
                float4 f = w4[(size_t)(n0 + dd) * 192 + (k0 >> 2) + kv];
                Ws[dd][kv * 4 + 0] = f.x;
                Ws[dd][kv * 4 + 1] = f.y;
                Ws[dd][kv * 4 + 2] = f.z;
                Ws[dd][kv * 4 + 3] = f.w;
            }
            __syncthreads();
            #pragma unroll
            for (int kk = 0; kk < 32; kk++) {
                float a0 = As[ty * 2 + 0][kk];
                float a1 = As[ty * 2 + 1][kk];
                #pragma unroll
                for (int j = 0; j < 4; j++) {
                    float wv = Ws[tx * 4 + j][kk];
                    acc[0][j] += a0 * wv;
                    acc[1][j] += a1 * wv;
                }
            }
            __syncthreads();
        }
        #pragma unroll
        for (int r = 0; r < 2; r++) {
            #pragma unroll
            for (int j = 0; j < 4; j++) {
                int m = m0 + ty * 2 + r;
                int d = n0 + tx * 4 + j;
                g_pembed[m * DD + d] = acc[r][j] + bias[d];
            }
        }
    } else if (bx == 48) {
        int warp = t >> 5, lane = t & 31;
        for (int p = warp; p < PP; p += 8) {
            const float* row = pkey + (size_t)p * DD;
            float sq = 0.f;
            for (int k = lane; k < DD; k += 32) { float v = row[k]; sq += v * v; }
            #pragma unroll
            for (int o = 16; o; o >>= 1) sq += __shfl_xor_sync(0xffffffffu, sq, o);
            float rs = rsqrtf(fmaxf(sq, 1e-12f));
            for (int k = lane; k < DD; k += 32) g_pnorm[p * DD + k] = row[k] * rs;
        }
    } else {
        int b = bx - 49;
        if (t < 192) {
            const float4* src = reinterpret_cast<const float4*>(x)
                                + (size_t)b * NN * 192 + t;
            float4* dst = reinterpret_cast<float4*>(out)
                          + ((size_t)b * 216 + 20) * 192 + t;
            float4 acc = make_float4(0.f, 0.f, 0.f, 0.f);
            #pragma unroll 1
            for (int n = 0; n < NN; n += 7) {     // 196 = 28 * 7, deep MLP
                float4 v[7];
                #pragma unroll
                for (int u = 0; u < 7; u++) v[u] = __ldcs(&src[(size_t)(n + u) * 192]);
                #pragma unroll
                for (int u = 0; u < 7; u++) {
                    __stcs(&dst[(size_t)(n + u) * 192], v[u]);
                    acc.x += v[u].x; acc.y += v[u].y;
                    acc.z += v[u].z; acc.w += v[u].w;
                }
            }
            const float inv = 1.0f / 196.0f;
            acc.x *= inv; acc.y *= inv; acc.z *= inv; acc.w *= inv;
            reinterpret_cast<float4*>(g_mean)[(size_t)b * 192 + t] = acc;
        }
    }
}

// ---------------------------------------------------------------------------
// Sim + top-5 + reduce_sim, batched: 32 blocks x 8 batches.
// pnorm read once per BLOCK (3 MB total vs 25 MB before); each loaded pnorm
// value feeds 8 FMAs against smem-resident means.
// ---------------------------------------------------------------------------
__global__ __launch_bounds__(256) void sim_topk_kernel(float* __restrict__ out)
{
    __shared__ __align__(16) float sx[8][DD];     // 8 mean rows (24.5 KB)
    __shared__ float s_rs[8];
    __shared__ float s_sim[8][PP];
    __shared__ float s_red[8];
    __shared__ int   s_last;

    const int t = threadIdx.x;
    const int warp = t >> 5, lane = t & 31;
    const int b0 = blockIdx.x * 8;
    const unsigned FULL = 0xffffffffu;

    // ---- stage 8 mean rows into smem (1536 float4, 6 per thread)
    {
        const float4* gm4 = reinterpret_cast<const float4*>(g_mean) + (size_t)b0 * 192;
        float4* sx4 = reinterpret_cast<float4*>(&sx[0][0]);
        #pragma unroll
        for (int e = t; e < 8 * 192; e += 256) sx4[e] = gm4[e];
    }
    __syncthreads();

    // ---- warp w computes rsqrt norm of mean row w
    {
        float sq = 0.f;
        #pragma unroll
        for (int i = 0; i < DD / 32; i++) {
            float v = sx[warp][lane + i * 32];
            sq += v * v;
        }
        #pragma unroll
        for (int o = 16; o; o >>= 1) sq += __shfl_xor_sync(FULL, sq, o);
        if (lane == 0) s_rs[warp] = rsqrtf(fmaxf(sq, 1e-12f));
    }
    __syncthreads();

    // ---- sim block: warp w handles pool rows {w, w+8, w+16, w+24} x 8 batches
    {
        const float* __restrict__ pn0 = g_pnorm + (size_t)(warp +  0) * DD;
        const float* __restrict__ pn1 = g_pnorm + (size_t)(warp +  8) * DD;
        const float* __restrict__ pn2 = g_pnorm + (size_t)(warp + 16) * DD;
        const float* __restrict__ pn3 = g_pnorm + (size_t)(warp + 24) * DD;
        float acc[4][8];
        #pragma unroll
        for (int j = 0; j < 4; j++)
            #pragma unroll
            for (int r = 0; r < 8; r++) acc[j][r] = 0.f;

        #pragma unroll
        for (int i = 0; i < DD / 32; i++) {
            int k = lane + i * 32;
            float pv0 = __ldg(pn0 + k);
            float pv1 = __ldg(pn1 + k);
            float pv2 = __ldg(pn2 + k);
            float pv3 = __ldg(pn3 + k);
            #pragma unroll
            for (int r = 0; r < 8; r++) {
                float xv = sx[r][k];
                acc[0][r] += pv0 * xv;
                acc[1][r] += pv1 * xv;
                acc[2][r] += pv2 * xv;
                acc[3][r] += pv3 * xv;
            }
        }
        #pragma unroll
        for (int j = 0; j < 4; j++) {
            #pragma unroll
            for (int r = 0; r < 8; r++) {
                float v = acc[j][r];
                #pragma unroll
                for (int o = 16; o; o >>= 1) v += __shfl_xor_sync(FULL, v, o);
                if (lane == 0) s_sim[r][warp + 8 * j] = v * s_rs[r];
            }
        }
    }
    __syncthreads();

    // ---- write similarity rows (scalar: O_SIM is odd float offset)
    {
        int r = t >> 5, p = t & 31;
        out[O_SIM + (size_t)(b0 + r) * PP + p] = s_sim[r][p];
    }

    // ---- top-5: warp w handles batch b0+w (iterative argmax, low idx wins)
    {
        const int b = b0 + warp;
        float v = s_sim[warp][lane];
        unsigned sel = 0u;
        float lsum = 0.f;
        #pragma unroll
        for (int k = 0; k < TOPK; k++) {
            float bv = ((sel >> lane) & 1u) ? -__int_as_float(0x7f800000) : v;
            int   bi = lane;
            #pragma unroll
            for (int o = 16; o; o >>= 1) {
                float ov = __shfl_xor_sync(FULL, bv, o);
                int   oi = __shfl_xor_sync(FULL, bi, o);
                if (ov > bv || (ov == bv && oi < bi)) { bv = ov; bi = oi; }
            }
            sel |= 1u << bi;
            if (lane == 0) {
                g_idx[b * TOPK + k] = bi;
                out[O_IDX + (size_t)b * TOPK + k] = (float)bi;
                lsum += bv;
            }
        }
        if (lane == 0) g_rs[b] = lsum;
    }
    __syncthreads();

    // ---- deterministic reduce_sim: last of 32 blocks sums 256 in fixed order
    if (t == 0) {
        __threadfence();
        int old = atomicAdd(&g_counter, 1);
        s_last = (old == 31);
    }
    __syncthreads();
    if (s_last) {
        __threadfence();
        float v = g_rs[t];
        #pragma unroll
        for (int o = 16; o; o >>= 1) v += __shfl_xor_sync(FULL, v, o);
        if (lane == 0) s_red[warp] = v;
        __syncthreads();
        if (t == 0) {
            float tot = 0.f;
            #pragma unroll
            for (int wv = 0; wv < 8; wv++) tot += s_red[wv];
            out[O_RS] = tot / (float)BB;
            g_counter = 0;                       // reset for next graph replay
        }
    }
}

// ---------------------------------------------------------------------------
// Gather: block b copies 20 prompt-embed rows into out rows [0,20). L2-hot.
// ---------------------------------------------------------------------------
__global__ __launch_bounds__(192) void gather_kernel(float* __restrict__ out)
{
    __shared__ int s_idx[TOPK];
    const int b = blockIdx.x, t = threadIdx.x;
    if (t < TOPK) s_idx[t] = g_idx[b * TOPK + t];
    __syncthreads();

    const float4* pe4 = reinterpret_cast<const float4*>(g_pembed);
    float4* ob4 = reinterpret_cast<float4*>(out) + (size_t)b * 216 * 192;
    #pragma unroll
    for (int j = 0; j < 20; j++) {
        int i = s_idx[j >> 2];
        int row = i * 4 + (j & 3);
        ob4[(size_t)j * 192 + t] = __ldg(pe4 + (size_t)row * 192 + t);
    }
}

// ---------------------------------------------------------------------------
extern "C" void kernel_launch(void* const* d_in, const int* in_sizes, int n_in,
                              void* d_out, int out_size)
{
    const float* x      = (const float*)d_in[0];  // x_embed  (256,196,768)
    const float* prompt = (const float*)d_in[1];  // prompt   (32,3,32,32)
    const float* pkey   = (const float*)d_in[2];  // prompt_key (32,768)
    const float* w      = (const float*)d_in[3];  // conv_w   (768,3,16,16)
    const float* bias   = (const float*)d_in[4];  // conv_b   (768)
    float* out = (float*)d_out;

    mega_kernel<<<49 + BB, 256>>>(x, prompt, pkey, w, bias, out);
    sim_topk_kernel<<<PP, 256>>>(out);
    gather_kernel<<<BB, 192>>>(out);
}

// round 11
// speedup vs baseline: 1.1593x; 1.1296x over previous
#include <cuda_runtime.h>

// Problem constants
#define BB   256   // batch
#define NN   196   // tokens
#define QR   49    // rows per copy unit (quarter batch; 196 = 4*49)
#define NU   1024  // copy units = BB*4
#define DD   768   // dim
#define PP   32    // pool size
#define TOPK 5
#define MM   128   // PP*4 rows of patch-embed GEMM
#define KDIM 768   // 3*16*16

#define NBLK 305                       // 48 GEMM + 1 pnorm + 256 tail-owner blocks
#define TICKS_PER_LAUNCH (NU + NBLK)   // exact ticket consumption per launch

// Output layout (flattened tuple, float32):
//   prompted_embedding (256,216,768) | reduce_sim (1) | similarity (256,32) | idx (256,5)
#define O_RS  (42467328ll)
#define O_SIM (O_RS + 1)          // odd float offset -> 4B-aligned only; scalar stores
#define O_IDX (O_SIM + (long long)BB * PP)

// Scratch (static device globals — no allocation allowed); float4-touched => align 16
__device__ __align__(16) float g_pembed[MM * DD];    // patch-embed result (128,768)
__device__ __align__(16) float g_pnorm[PP * DD];     // l2-normalized prompt_key
__device__ __align__(16) float g_mpart[4][BB][DD];   // per-quarter partial row sums
__device__ __align__(16) float g_rs[BB];             // per-batch top-5 sim sums
__device__ int      g_bcnt[BB];    // per-batch quarter-completion counters
__device__ int      g_ready;       // producer completion counter (reset by last tail)
__device__ int      g_counter;     // tail completion counter (reset by last tail)
__device__ unsigned g_ticket;      // monotonic ticket; modulo per launch

// ---------------------------------------------------------------------------
// One kernel, three phases:
//  P1  blocks [0,48): patch-embed GEMM -> g_pembed; block 48: pnorm; signal.
//  P2  ALL blocks steal fixed 49-row copy units (ticket). Unit boundaries are
//      fixed -> partial sums deterministic no matter which block runs them.
//  P3  block 49+b waits for batch b's 4 units + producers, then sim+top5+
//      gather for batch b (overlaps remaining copies on other SMs).
// ---------------------------------------------------------------------------
__global__ void __launch_bounds__(256) fused_kernel(
    const float* __restrict__ x,       // (256,196,768)
    const float* __restrict__ prompt,  // (32,3,32,32)
    const float* __restrict__ pkey,    // (32,768)
    const float* __restrict__ w,       // (768,3,16,16) == (768,768) row-major
    const float* __restrict__ bias,    // (768)
    float* __restrict__ out)
{
    const int bx = blockIdx.x;
    const int t  = threadIdx.x;
    const int warp = t >> 5, lane = t & 31;
    const unsigned FULL = 0xffffffffu;

    // ============================ P1: producers ============================
    if (bx < 48) {
        __shared__ __align__(16) float As[32][33];
        __shared__ __align__(16) float Ws[64][33];
        const int m0 = (bx / 12) * 32;
        const int n0 = (bx % 12) * 64;
        const int tx = t & 15;
        const int ty = t >> 4;
        float acc[2][4] = {{0.f,0.f,0.f,0.f},{0.f,0.f,0.f,0.f}};

        const float4* w4 = reinterpret_cast<const float4*>(w);

        for (int k0 = 0; k0 < KDIM; k0 += 32) {
            #pragma unroll
            for (int s = 0; s < 4; s++) {
                int e  = s * 256 + t;
                int mm = e >> 5;
                int kk = e & 31;
                int m  = m0 + mm;
                int p  = m >> 2;
                int l  = m & 3;
                int py = l >> 1, px = l & 1;
                int k  = k0 + kk;
                int c  = k >> 8;
                int rem = k & 255;
                int ii = rem >> 4, jj = rem & 15;
                As[mm][kk] = prompt[((size_t)(p * 3 + c) * 32 + py * 16 + ii) * 32
                                    + px * 16 + jj];
            }
            #pragma unroll
            for (int s = 0; s < 2; s++) {
                int v  = s * 256 + t;
                int dd = v >> 3;
                int kv = v & 7;
                float4 f = w4[(size_t)(n0 + dd) * 192 + (k0 >> 2) + kv];
                Ws[dd][kv * 4 + 0] = f.x;
                Ws[dd][kv * 4 + 1] = f.y;
                Ws[dd][kv * 4 + 2] = f.z;
                Ws[dd][kv * 4 + 3] = f.w;
            }
            __syncthreads();
            #pragma unroll
            for (int kk = 0; kk < 32; kk++) {
                float a0 = As[ty * 2 + 0][kk];
                float a1 = As[ty * 2 + 1][kk];
                #pragma unroll
                for (int j = 0; j < 4; j++) {
                    float wv = Ws[tx * 4 + j][kk];
                    acc[0][j] += a0 * wv;
                    acc[1][j] += a1 * wv;
                }
            }
            __syncthreads();
        }
        #pragma unroll
        for (int r = 0; r < 2; r++) {
            #pragma unroll
            for (int j = 0; j < 4; j++) {
                int m = m0 + ty * 2 + r;
                int d = n0 + tx * 4 + j;
                g_pembed[m * DD + d] = acc[r][j] + bias[d];
            }
        }
        __syncthreads();
        __threadfence();
        if (t == 0) atomicAdd(&g_ready, 1);

    } else if (bx == 48) {
        for (int p = warp; p < PP; p += 8) {
            const float* row = pkey + (size_t)p * DD;
            float sq = 0.f;
            for (int k = lane; k < DD; k += 32) { float v = row[k]; sq += v * v; }
            #pragma unroll
            for (int o = 16; o; o >>= 1) sq += __shfl_xor_sync(FULL, sq, o);
            float rs = rsqrtf(fmaxf(sq, 1e-12f));
            for (int k = lane; k < DD; k += 32) g_pnorm[p * DD + k] = row[k] * rs;
        }
        __syncthreads();
        __threadfence();
        if (t == 0) atomicAdd(&g_ready, 1);
    }

    // ================== P2: work-stealing copy (ALL blocks) =================
    __shared__ unsigned s_u;
    for (;;) {
        if (t == 0) s_u = atomicAdd(&g_ticket, 1u) % TICKS_PER_LAUNCH;
        __syncthreads();
        const unsigned u = s_u;
        __syncthreads();                       // protect s_u before next grab
        if (u >= NU) break;                    // exactly one exit grab per block

        const int cb = (int)(u >> 2);
        const int q  = (int)(u & 3);
        const int r0 = q * QR;

        if (t < 192) {
            const float4* src = reinterpret_cast<const float4*>(x)
                                + ((size_t)cb * NN + r0) * 192 + t;
            float4* dst = reinterpret_cast<float4*>(out)
                          + ((size_t)cb * 216 + 20 + r0) * 192 + t;
            float4 acc = make_float4(0.f, 0.f, 0.f, 0.f);
            #pragma unroll 1
            for (int n = 0; n < QR; n += 7) {     // 49 = 7*7, deep MLP
                float4 v[7];
                #pragma unroll
                for (int e = 0; e < 7; e++) v[e] = __ldcs(&src[(size_t)(n + e) * 192]);
                #pragma unroll
                for (int e = 0; e < 7; e++) {
                    __stcs(&dst[(size_t)(n + e) * 192], v[e]);
                    acc.x += v[e].x; acc.y += v[e].y;
                    acc.z += v[e].z; acc.w += v[e].w;
                }
            }
            reinterpret_cast<float4*>(g_mpart[q][cb])[t] = acc;
        }
        __syncthreads();
        __threadfence();
        if (t == 0) atomicAdd(&g_bcnt[cb], 1);
    }

    // ===================== P3: per-batch tail (256 blocks) ==================
    if (bx < 49) return;
    const int b = bx - 49;

    __shared__ __align__(16) float sx[DD];
    __shared__ float s_red[8];
    __shared__ float s_sim[PP];
    __shared__ int   s_idx[TOPK];
    __shared__ int   s_last;

    // wait for this batch's 4 copy units + producers (all blocks co-resident)
    if (t == 0) {
        while (atomicAdd(&g_bcnt[b], 0) < 4 || atomicAdd(&g_ready, 0) < 49) { }
        g_bcnt[b] = 0;                          // reset for next launch
    }
    __syncthreads();
    __threadfence();

    // combine quarter partials -> mean (fixed order -> deterministic)
    if (t < 192) {
        const float4* p0 = reinterpret_cast<const float4*>(g_mpart[0][b]);
        const float4* p1 = reinterpret_cast<const float4*>(g_mpart[1][b]);
        const float4* p2 = reinterpret_cast<const float4*>(g_mpart[2][b]);
        const float4* p3 = reinterpret_cast<const float4*>(g_mpart[3][b]);
        float4 a = p0[t], c1 = p1[t], c2 = p2[t], c3 = p3[t];
        const float inv = 1.0f / 196.0f;
        a.x = ((a.x + c1.x) + (c2.x + c3.x)) * inv;
        a.y = ((a.y + c1.y) + (c2.y + c3.y)) * inv;
        a.z = ((a.z + c1.z) + (c2.z + c3.z)) * inv;
        a.w = ((a.w + c1.w) + (c2.w + c3.w)) * inv;
        reinterpret_cast<float4*>(sx)[t] = a;
    }
    __syncthreads();

    // squared norm of mean
    float sq = 0.f;
    #pragma unroll
    for (int i = 0; i < 3; i++) {
        float v = sx[t + i * 256];
        sq += v * v;
    }
    #pragma unroll
    for (int o = 16; o; o >>= 1) sq += __shfl_xor_sync(FULL, sq, o);
    if (lane == 0) s_red[warp] = sq;
    __syncthreads();
    float rv = (lane < 8) ? s_red[lane] : 0.f;
    #pragma unroll
    for (int o = 4; o; o >>= 1) rv += __shfl_xor_sync(FULL, rv, o);
    const float rs = rsqrtf(fmaxf(__shfl_sync(FULL, rv, 0), 1e-12f));

    // similarity: warp w owns pool rows 4w..4w+3, interleaved dots (MLP high)
    {
        const float* __restrict__ pn0 = g_pnorm + (size_t)(warp * 4 + 0) * DD;
        const float* __restrict__ pn1 = g_pnorm + (size_t)(warp * 4 + 1) * DD;
        const float* __restrict__ pn2 = g_pnorm + (size_t)(warp * 4 + 2) * DD;
        const float* __restrict__ pn3 = g_pnorm + (size_t)(warp * 4 + 3) * DD;
        float d0 = 0.f, d1 = 0.f, d2 = 0.f, d3 = 0.f;
        #pragma unroll
        for (int i = 0; i < DD / 32; i++) {
            int k = lane + i * 32;
            float xv = sx[k];
            d0 += xv * __ldg(pn0 + k);
            d1 += xv * __ldg(pn1 + k);
            d2 += xv * __ldg(pn2 + k);
            d3 += xv * __ldg(pn3 + k);
        }
        #pragma unroll
        for (int o = 16; o; o >>= 1) {
            d0 += __shfl_xor_sync(FULL, d0, o);
            d1 += __shfl_xor_sync(FULL, d1, o);
            d2 += __shfl_xor_sync(FULL, d2, o);
            d3 += __shfl_xor_sync(FULL, d3, o);
        }
        if (lane == 0) {
            int p = warp * 4;
            float v0 = d0 * rs, v1 = d1 * rs, v2 = d2 * rs, v3 = d3 * rs;
            s_sim[p + 0] = v0; s_sim[p + 1] = v1;
            s_sim[p + 2] = v2; s_sim[p + 3] = v3;
            float* so = out + O_SIM + (size_t)b * PP + p;   // 4B-aligned only
            so[0] = v0; so[1] = v1; so[2] = v2; so[3] = v3;
        }
    }
    __syncthreads();

    // top-5 (warp 0): iterative argmax, lower index wins ties
    if (warp == 0) {
        float v = s_sim[lane];
        unsigned sel = 0u;
        float lsum = 0.f;
        #pragma unroll
        for (int k = 0; k < TOPK; k++) {
            float bv = ((sel >> lane) & 1u) ? -__int_as_float(0x7f800000) : v;
            int   bi = lane;
            #pragma unroll
            for (int o = 16; o; o >>= 1) {
                float ov = __shfl_xor_sync(FULL, bv, o);
                int   oi = __shfl_xor_sync(FULL, bi, o);
                if (ov > bv || (ov == bv && oi < bi)) { bv = ov; bi = oi; }
            }
            sel |= 1u << bi;
            if (lane == 0) {
                s_idx[k] = bi;
                out[O_IDX + (size_t)b * TOPK + k] = (float)bi;
                lsum += bv;
            }
        }
        if (lane == 0) g_rs[b] = lsum;
    }
    __syncthreads();

    // gather 20 rows (5 prompts x 4 patches) into out rows [0,20)
    {
        const float4* pe4 = reinterpret_cast<const float4*>(g_pembed);
        float4* ob4 = reinterpret_cast<float4*>(out) + (size_t)b * 216 * 192;
        #pragma unroll
        for (int e = t; e < 20 * 192; e += 256) {
            int j = e / 192;
            int c = e - j * 192;
            int i = s_idx[j >> 2];
            int row = i * 4 + (j & 3);
            ob4[(size_t)j * 192 + c] = __ldg(pe4 + (size_t)row * 192 + c);
        }
    }

    // deterministic reduce_sim: last tail sums g_rs in fixed order
    if (t == 0) {
        __threadfence();
        int old = atomicAdd(&g_counter, 1);
        s_last = (old == BB - 1);
    }
    __syncthreads();
    if (s_last) {
        __threadfence();
        float v = g_rs[t];
        #pragma unroll
        for (int o = 16; o; o >>= 1) v += __shfl_xor_sync(FULL, v, o);
        if (lane == 0) s_red[warp] = v;
        __syncthreads();
        if (t == 0) {
            float tot = 0.f;
            #pragma unroll
            for (int wv = 0; wv < 8; wv++) tot += s_red[wv];
            out[O_RS] = tot / (float)BB;
            g_counter = 0;                      // reset for next launch
            g_ready   = 0;
        }
    }
}

// ---------------------------------------------------------------------------
extern "C" void kernel_launch(void* const* d_in, const int* in_sizes, int n_in,
                              void* d_out, int out_size)
{
    const float* x      = (const float*)d_in[0];  // x_embed  (256,196,768)
    const float* prompt = (const float*)d_in[1];  // prompt   (32,3,32,32)
    const float* pkey   = (const float*)d_in[2];  // prompt_key (32,768)
    const float* w      = (const float*)d_in[3];  // conv_w   (768,3,16,16)
    const float* bias   = (const float*)d_in[4];  // conv_b   (768)
    float* out = (float*)d_out;

    fused_kernel<<<NBLK, 256>>>(x, prompt, pkey, w, bias, out);
}